// round 16
// baseline (speedup 1.0000x reference)
#include <cuda_runtime.h>
#include <cuda_bf16.h>
#include <cstdint>

// VectorQuantizer: x[131072,64] f32, W[1024,64] f32.
// out = [quantized(N,64) | quantized(N,64) | indices-as-f32(N)]
// argmin_k ||f-w_k||^2 == argmax_k ( f.w_k - 0.5||w_k||^2 )
// R16: R14 body (3-pass bf16 screening, keyed FMNMX top-2, exact fp32
//      rescore) + wave-quantization fix: 888 CTAs x 128 rows (3 exact waves)
//      then 272 CTAs x 64 rows (one half-duration wave).

#define NROWS   131072
#define DIM     64
#define NCODE   1024
#define WINDOW  128
#define NWIN    (NCODE / WINDOW)        // 8

#define ROWB    144                     // padded row stride (72 bf16)
#define SPLIT_W (WINDOW * ROWB)         // 18432 per split
#define BUF_W   (2 * SPLIT_W)           // 36864 (h,m splits)
// [0, BUF_W) : A staging (2 splits, first 2*MCTA*ROWB bytes); aliased as B
//              buffer for ODD windows (A frags live in regs by then).
#define SM_BUF1 BUF_W                   // B buffer for EVEN windows
#define SM_BIAS (SM_BUF1 + BUF_W)       // 73728, two 512B slots
#define SMEM_TOTAL (SM_BIAS + 1024)     // 74752

#define NB1     888                     // 128-row CTAs (= 3 * 296 slots)
#define NB2     272                     // 64-row CTAs
#define ROWBASE2 (NB1 * 128)            // 113664

__device__ __align__(16) __nv_bfloat16 g_Wsplit[2][NCODE][DIM];   // h, m
__device__ __align__(16) float g_bias[NCODE];                     // -0.5||w||^2

// ---- helpers ---------------------------------------------------------------
__device__ __forceinline__ uint32_t smem_to_u32(const void* p) {
    uint32_t a;
    asm("{ .reg .u64 t; cvta.to.shared.u64 t, %1; cvt.u32.u64 %0, t; }" : "=r"(a) : "l"(p));
    return a;
}
__device__ __forceinline__ void split2(float v, __nv_bfloat16& h, __nv_bfloat16& m) {
    h = __float2bfloat16_rn(v);
    m = __float2bfloat16_rn(v - __bfloat162float(h));
}
__device__ __forceinline__ uint32_t pack2(__nv_bfloat16 a, __nv_bfloat16 b) {
    __nv_bfloat162 t = __halves2bfloat162(a, b);
    return *reinterpret_cast<uint32_t*>(&t);
}
__device__ __forceinline__ bool beats(float av, int ai, float bv, int bi) {
    return av > bv || (av == bv && ai < bi);
}
// embed 4-bit local id into low mantissa bits (order-preserving to 16 ulps)
__device__ __forceinline__ float embed4(float v, int lid) {
    return __uint_as_float((__float_as_uint(v) & 0xFFFFFFF0u) | (uint32_t)lid);
}
#define LDSM_X4(r0, r1, r2, r3, a) \
    asm volatile("ldmatrix.sync.aligned.m8n8.x4.shared.b16 {%0,%1,%2,%3}, [%4];" \
                 : "=r"(r0), "=r"(r1), "=r"(r2), "=r"(r3) : "r"(a))
#define MMA_BF16(d, a, b) \
    asm volatile("mma.sync.aligned.m16n8k16.row.col.f32.bf16.bf16.f32 " \
                 "{%0,%1,%2,%3}, {%4,%5,%6,%7}, {%8,%9}, {%0,%1,%2,%3};" \
                 : "+f"((d)[0]), "+f"((d)[1]), "+f"((d)[2]), "+f"((d)[3]) \
                 : "r"((a)[0]), "r"((a)[1]), "r"((a)[2]), "r"((a)[3]), "r"((b)[0]), "r"((b)[1]))
#define CP_ASYNC16(dst, src) \
    asm volatile("cp.async.cg.shared.global [%0], [%1], 16;" \
                 :: "r"((uint32_t)(dst)), "l"((size_t)__cvta_generic_to_global(src)) : "memory")
#define CP_COMMIT() asm volatile("cp.async.commit_group;" ::: "memory")
#define CP_WAIT0()  asm volatile("cp.async.wait_group 0;" ::: "memory")

// ---- prep: split codebook (h,m) + fp32 bias ---------------------------------
__global__ void prep_kernel(const float* __restrict__ W) {
    int k = blockIdx.x * blockDim.x + threadIdx.x;
    if (k >= NCODE) return;
    float s = 0.0f;
#pragma unroll
    for (int d = 0; d < DIM; d++) {
        float v = W[(size_t)k * DIM + d];
        __nv_bfloat16 h, m;
        split2(v, h, m);
        g_Wsplit[0][k][d] = h; g_Wsplit[1][k][d] = m;
        s = fmaf(v, v, s);
    }
    g_bias[k] = -0.5f * s;
}

// issue cp.async for window w (codes [kbase, kbase+128)), 2 splits
template<int THREADS_>
__device__ __forceinline__ void prefetch_win(uint32_t sbase, int w, int kbase, int tid) {
    const char* gw = reinterpret_cast<const char*>(g_Wsplit);
    const uint32_t base = sbase + (((w & 1) == 0) ? SM_BUF1 : 0);
#pragma unroll
    for (int t = 0; t < 2048 / THREADS_; t++) {
        int i = tid + t * THREADS_;                // 0..2047
        int split = i >> 10, rem = i & 1023;
        int n = rem >> 3, ch = rem & 7;
        uint32_t dst = base + split * SPLIT_W + n * ROWB + ch * 16;
        const char* src = gw + (((size_t)split * NCODE + kbase + n) * 8 + ch) * 16;
        CP_ASYNC16(dst, src);
    }
    if (tid < 32)
        CP_ASYNC16(sbase + SM_BIAS + (w & 1) * 512 + tid * 16,
                   reinterpret_cast<const char*>(g_bias) + (size_t)kbase * 4 + tid * 16);
    CP_COMMIT();
}

// ---- main kernel (MCTA_ = THREADS_/2 rows per CTA) ---------------------------
template<int MCTA_, int THREADS_>
__global__ __launch_bounds__(THREADS_, 2)
void vq_kernel(const float* __restrict__ x,
               const float* __restrict__ W,
               float* __restrict__ out,
               int rowbase) {
    static_assert(MCTA_ * 2 == THREADS_, "staging mapping requires MCTA = THREADS/2");
    constexpr int SPLIT_A = MCTA_ * ROWB;
    extern __shared__ char smem[];
    const uint32_t sbase = smem_to_u32(smem);
    const int tid  = threadIdx.x;
    const int lane = tid & 31;
    const int wid  = tid >> 5;
    const int wm   = wid * 16;          // 16 rows per warp
    const int ctabase = rowbase + blockIdx.x * MCTA_;

    prefetch_win<THREADS_>(sbase, 0, 0, tid);   // window 0 -> dedicated buffer

    // ---- stage A rows (h,m splits) into [0, 2*SPLIT_A) ----
    {
        const int row = tid >> 1, half = tid & 1;   // rows 0..MCTA_-1
        const float4* xr = reinterpret_cast<const float4*>(
            x + ((size_t)ctabase + row) * DIM + half * 32);
        char* a0 = smem + row * ROWB + half * 64;
#pragma unroll
        for (int i = 0; i < 8; i++) {
            float4 v = xr[i];
            __nv_bfloat16 h0, m0, h1, m1, h2, m2, h3, m3;
            split2(v.x, h0, m0); split2(v.y, h1, m1);
            split2(v.z, h2, m2); split2(v.w, h3, m3);
            *reinterpret_cast<uint32_t*>(a0 + i * 8)               = pack2(h0, h1);
            *reinterpret_cast<uint32_t*>(a0 + i * 8 + 4)           = pack2(h2, h3);
            *reinterpret_cast<uint32_t*>(a0 + SPLIT_A + i * 8)     = pack2(m0, m1);
            *reinterpret_cast<uint32_t*>(a0 + SPLIT_A + i * 8 + 4) = pack2(m2, m3);
        }
    }
    __syncthreads();

    // ---- A fragments (h,m) -> registers, persistent ----
    uint32_t Af[2][4][4];
    {
        const uint32_t aB = sbase + (uint32_t)(wm + (lane & 15)) * ROWB + (lane >> 4) * 16;
#pragma unroll
        for (int sa = 0; sa < 2; sa++)
#pragma unroll
            for (int k = 0; k < 4; k++)
                LDSM_X4(Af[sa][k][0], Af[sa][k][1], Af[sa][k][2], Af[sa][k][3],
                        aB + sa * SPLIT_A + k * 32);
    }

    // running top-2 per row-chain (q=0: row wm+(lane>>2), q=1: +8)
    float b1[2] = {-3.0e38f, -3.0e38f}, b2[2] = {-3.0e38f, -3.0e38f};
    int   i1[2] = {0, 0},               i2[2] = {1, 1};

    const uint32_t blane = (uint32_t)(((lane >> 4) & 1) * 8 + (lane & 7)) * ROWB
                         + ((lane >> 3) & 1) * 16;

    for (int w = 0; w < NWIN; w++) {
        CP_WAIT0();
        __syncthreads();
        if (w + 1 < NWIN)
            prefetch_win<THREADS_>(sbase, w + 1, (w + 1) * WINDOW, tid);

        const uint32_t bufb = sbase + (((w & 1) == 0) ? SM_BUF1 : 0);
        const float* sBias = reinterpret_cast<const float*>(smem + SM_BIAS + (w & 1) * 512);

#pragma unroll
        for (int sc = 0; sc < 2; sc++) {       // two 64-code sub-chunks
            float acc[8][4];
#pragma unroll
            for (int nt = 0; nt < 8; nt++) {
                float2 bb = *reinterpret_cast<const float2*>(
                    &sBias[sc * 64 + nt * 8 + (lane & 3) * 2]);
                acc[nt][0] = bb.x; acc[nt][1] = bb.y;
                acc[nt][2] = bb.x; acc[nt][3] = bb.y;
            }

            const uint32_t bbc = bufb + sc * 64 * ROWB + blane;
#pragma unroll
            for (int k = 0; k < 4; k++) {
#pragma unroll
                for (int np = 0; np < 2; np++) {
                    uint32_t Bh0[4], Bh1[4], Bm0[4], Bm1[4];
                    uint32_t bB = bbc + np * 32 * ROWB + k * 32;
                    LDSM_X4(Bh0[0], Bh0[1], Bh0[2], Bh0[3], bB);
                    LDSM_X4(Bh1[0], Bh1[1], Bh1[2], Bh1[3], bB + 16 * ROWB);
                    LDSM_X4(Bm0[0], Bm0[1], Bm0[2], Bm0[3], bB + SPLIT_W);
                    LDSM_X4(Bm1[0], Bm1[1], Bm1[2], Bm1[3], bB + SPLIT_W + 16 * ROWB);
                    // hh
                    MMA_BF16(acc[4 * np + 0], Af[0][k], Bh0);
                    MMA_BF16(acc[4 * np + 1], Af[0][k], Bh0 + 2);
                    MMA_BF16(acc[4 * np + 2], Af[0][k], Bh1);
                    MMA_BF16(acc[4 * np + 3], Af[0][k], Bh1 + 2);
                    // mh
                    MMA_BF16(acc[4 * np + 0], Af[1][k], Bh0);
                    MMA_BF16(acc[4 * np + 1], Af[1][k], Bh0 + 2);
                    MMA_BF16(acc[4 * np + 2], Af[1][k], Bh1);
                    MMA_BF16(acc[4 * np + 3], Af[1][k], Bh1 + 2);
                    // hm
                    MMA_BF16(acc[4 * np + 0], Af[0][k], Bm0);
                    MMA_BF16(acc[4 * np + 1], Af[0][k], Bm0 + 2);
                    MMA_BF16(acc[4 * np + 2], Af[0][k], Bm1);
                    MMA_BF16(acc[4 * np + 3], Af[0][k], Bm1 + 2);
                }
            }

            // ---- branchless keyed top-2 per chain ----
            const int nbase = w * WINDOW + sc * 64;
#pragma unroll
            for (int q = 0; q < 2; q++) {
                float h[8], l[8];
#pragma unroll
                for (int nt = 0; nt < 8; nt++) {
                    float e0 = embed4(acc[nt][q * 2 + 0], nt * 2 + 0);
                    float e1 = embed4(acc[nt][q * 2 + 1], nt * 2 + 1);
                    h[nt] = fmaxf(e0, e1);
                    l[nt] = fminf(e0, e1);
                }
#pragma unroll
                for (int s = 1; s < 8; s <<= 1)
#pragma unroll
                    for (int i = 0; i < 8; i += 2 * s) {
                        float hm = fminf(h[i], h[i + s]);
                        h[i] = fmaxf(h[i], h[i + s]);
                        l[i] = fmaxf(hm, fmaxf(l[i], l[i + s]));
                    }
                int lid1 = (int)(__float_as_uint(h[0]) & 15u);
                int lid2 = (int)(__float_as_uint(l[0]) & 15u);
                float v1 = h[0], v2 = l[0];
                int n1 = nbase + (lid1 >> 1) * 8 + (lane & 3) * 2 + (lid1 & 1);
                int n2 = nbase + (lid2 >> 1) * 8 + (lane & 3) * 2 + (lid2 & 1);
                bool w1 = v1 > b1[q];
                float c  = w1 ? b1[q] : v1;    int ci  = w1 ? i1[q] : n1;
                float s2 = w1 ? v2    : b2[q]; int s2i = w1 ? n2    : i2[q];
                b1[q] = w1 ? v1 : b1[q];       i1[q] = w1 ? n1 : i1[q];
                bool cw = c > s2;
                b2[q] = cw ? c : s2;           i2[q] = cw ? ci : s2i;
            }
        }
    }

    // ---- quad merge: global top-2 per row across the 4 lanes ----
#pragma unroll
    for (int q = 0; q < 2; q++) {
#pragma unroll
        for (int off = 1; off < 4; off <<= 1) {
            float ob1 = __shfl_xor_sync(0xFFFFFFFFu, b1[q], off);
            int   oi1 = __shfl_xor_sync(0xFFFFFFFFu, i1[q], off);
            float ob2 = __shfl_xor_sync(0xFFFFFFFFu, b2[q], off);
            int   oi2 = __shfl_xor_sync(0xFFFFFFFFu, i2[q], off);
            bool ow = beats(ob1, oi1, b1[q], i1[q]);
            float nv1 = ow ? ob1 : b1[q];  int ni1 = ow ? oi1 : i1[q];
            float cv  = ow ? b1[q] : ob1;  int ci  = ow ? i1[q] : oi1;
            float sv  = ow ? ob2 : b2[q];  int si  = ow ? oi2 : i2[q];
            bool cw = beats(cv, ci, sv, si);
            b1[q] = nv1; i1[q] = ni1;
            b2[q] = cw ? cv : sv; i2[q] = cw ? ci : si;
        }
    }

    // ---- exact fp32 rescore of the two candidates ----
    int Kf[2];
#pragma unroll
    for (int q = 0; q < 2; q++) {
        const int r = wm + (lane >> 2) + q * 8;
        const size_t grow = (size_t)ctabase + r;
        const int c1 = i1[q], c2 = i2[q];
        float d1 = 0.0f, d2 = 0.0f;
#pragma unroll
        for (int k = 0; k < 4; k++)
#pragma unroll
            for (int ch = 0; ch < 2; ch++) {
                const int c0 = 2 * (lane & 3) + ch * 8 + 16 * k;
                float2 xx = *reinterpret_cast<const float2*>(x + grow * DIM + c0);
                float2 w1 = __ldg(reinterpret_cast<const float2*>(W + (size_t)c1 * DIM + c0));
                float2 w2 = __ldg(reinterpret_cast<const float2*>(W + (size_t)c2 * DIM + c0));
                d1 = fmaf(xx.x, w1.x, fmaf(xx.y, w1.y, d1));
                d2 = fmaf(xx.x, w2.x, fmaf(xx.y, w2.y, d2));
            }
        d1 += __shfl_xor_sync(0xFFFFFFFFu, d1, 1);
        d1 += __shfl_xor_sync(0xFFFFFFFFu, d1, 2);
        d2 += __shfl_xor_sync(0xFFFFFFFFu, d2, 1);
        d2 += __shfl_xor_sync(0xFFFFFFFFu, d2, 2);
        float s1 = d1 + __ldg(&g_bias[c1]);
        float s2 = d2 + __ldg(&g_bias[c2]);
        Kf[q] = beats(s1, c1, s2, c2) ? c1 : c2;
    }

    // ---- gather codewords + write outputs ----
    const int lq = lane & 3;   // dim slice lq*16 .. lq*16+15
#pragma unroll
    for (int q = 0; q < 2; q++) {
        const int r = wm + (lane >> 2) + q * 8;
        const size_t grow = (size_t)ctabase + r;
        const int K = Kf[q];
        const float4* wsrc = reinterpret_cast<const float4*>(W + (size_t)K * DIM + lq * 16);
        float4* o1 = reinterpret_cast<float4*>(out + grow * DIM + lq * 16);
        float4* o2 = reinterpret_cast<float4*>(out + ((size_t)NROWS + grow) * DIM + lq * 16);
#pragma unroll
        for (int i = 0; i < 4; i++) {
            float4 v = wsrc[i];
            o1[i] = v;
            o2[i] = v;
        }
        if (lq == 0)
            out[(size_t)2 * NROWS * DIM + grow] = (float)K;
    }
}

// ---- launch -----------------------------------------------------------------
extern "C" void kernel_launch(void* const* d_in, const int* in_sizes, int n_in,
                              void* d_out, int out_size) {
    const float* x = (const float*)d_in[0];
    const float* W = (const float*)d_in[1];
    float* out = (float*)d_out;

    cudaFuncSetAttribute(vq_kernel<128, 256>,
                         cudaFuncAttributeMaxDynamicSharedMemorySize, SMEM_TOTAL);
    cudaFuncSetAttribute(vq_kernel<64, 128>,
                         cudaFuncAttributeMaxDynamicSharedMemorySize, SMEM_TOTAL);

    prep_kernel<<<NCODE / 256, 256>>>(W);
    vq_kernel<128, 256><<<NB1, 256, SMEM_TOTAL>>>(x, W, out, 0);
    vq_kernel<64, 128><<<NB2, 128, SMEM_TOTAL>>>(x, W, out, ROWBASE2);
}

// round 17
// speedup vs baseline: 1.1422x; 1.1422x over previous
#include <cuda_runtime.h>
#include <cuda_bf16.h>
#include <cstdint>

// VectorQuantizer: x[131072,64] f32, W[1024,64] f32.
// out = [quantized(N,64) | quantized(N,64) | indices-as-f32(N)]
// argmin_k ||f-w_k||^2 == argmax_k ( f.w_k - 0.5||w_k||^2 )
// R17: R14 vq body (3-pass bf16 screening hh/hm/mh, keyed FMNMX top-2,
//      exact fp32 rescore) + warp-per-codeword prep (15us -> ~2us).

#define NROWS   131072
#define DIM     64
#define NCODE   1024
#define MCTA    128
#define WINDOW  128
#define NWIN    (NCODE / WINDOW)        // 8
#define THREADS 256

#define ROWB    144                     // padded row stride (72 bf16)
#define SPLIT_A (MCTA * ROWB)           // 18432 per split
#define SPLIT_W (WINDOW * ROWB)         // 18432 per split
#define BUF_W   (2 * SPLIT_W)           // 36864 (h,m splits)
// [0, 36864) : A staging (2 splits); aliased as B buffer for ODD windows
#define SM_BUF1 36864                   // B buffer for EVEN windows
#define SM_BIAS (SM_BUF1 + BUF_W)       // 73728, two 512B slots
#define SMEM_TOTAL (SM_BIAS + 1024)     // 74752

__device__ __align__(16) __nv_bfloat16 g_Wsplit[2][NCODE][DIM];   // h, m
__device__ __align__(16) float g_bias[NCODE];                     // -0.5||w||^2

// ---- helpers ---------------------------------------------------------------
__device__ __forceinline__ uint32_t smem_to_u32(const void* p) {
    uint32_t a;
    asm("{ .reg .u64 t; cvta.to.shared.u64 t, %1; cvt.u32.u64 %0, t; }" : "=r"(a) : "l"(p));
    return a;
}
__device__ __forceinline__ void split2(float v, __nv_bfloat16& h, __nv_bfloat16& m) {
    h = __float2bfloat16_rn(v);
    m = __float2bfloat16_rn(v - __bfloat162float(h));
}
__device__ __forceinline__ uint32_t pack2(__nv_bfloat16 a, __nv_bfloat16 b) {
    __nv_bfloat162 t = __halves2bfloat162(a, b);
    return *reinterpret_cast<uint32_t*>(&t);
}
__device__ __forceinline__ bool beats(float av, int ai, float bv, int bi) {
    return av > bv || (av == bv && ai < bi);
}
// embed 4-bit local id into low mantissa bits (order-preserving to 16 ulps)
__device__ __forceinline__ float embed4(float v, int lid) {
    return __uint_as_float((__float_as_uint(v) & 0xFFFFFFF0u) | (uint32_t)lid);
}
#define LDSM_X4(r0, r1, r2, r3, a) \
    asm volatile("ldmatrix.sync.aligned.m8n8.x4.shared.b16 {%0,%1,%2,%3}, [%4];" \
                 : "=r"(r0), "=r"(r1), "=r"(r2), "=r"(r3) : "r"(a))
#define MMA_BF16(d, a, b) \
    asm volatile("mma.sync.aligned.m16n8k16.row.col.f32.bf16.bf16.f32 " \
                 "{%0,%1,%2,%3}, {%4,%5,%6,%7}, {%8,%9}, {%0,%1,%2,%3};" \
                 : "+f"((d)[0]), "+f"((d)[1]), "+f"((d)[2]), "+f"((d)[3]) \
                 : "r"((a)[0]), "r"((a)[1]), "r"((a)[2]), "r"((a)[3]), "r"((b)[0]), "r"((b)[1]))
#define CP_ASYNC16(dst, src) \
    asm volatile("cp.async.cg.shared.global [%0], [%1], 16;" \
                 :: "r"((uint32_t)(dst)), "l"((size_t)__cvta_generic_to_global(src)) : "memory")
#define CP_COMMIT() asm volatile("cp.async.commit_group;" ::: "memory")
#define CP_WAIT0()  asm volatile("cp.async.wait_group 0;" ::: "memory")

// ---- prep: warp-per-codeword split + bias (fully parallel) -------------------
__global__ void prep_kernel(const float* __restrict__ W) {
    const int gid  = blockIdx.x * blockDim.x + threadIdx.x;   // 0..32767
    const int k    = gid >> 5;                                // codeword
    const int lane = gid & 31;                                // 2 dims per lane
    if (k >= NCODE) return;

    const float2 v = *reinterpret_cast<const float2*>(W + (size_t)k * DIM + lane * 2);
    float s = fmaf(v.x, v.x, v.y * v.y);
#pragma unroll
    for (int off = 16; off > 0; off >>= 1)
        s += __shfl_xor_sync(0xFFFFFFFFu, s, off);

    __nv_bfloat16 h0, m0, h1, m1;
    split2(v.x, h0, m0);
    split2(v.y, h1, m1);
    *reinterpret_cast<uint32_t*>(&g_Wsplit[0][k][lane * 2]) = pack2(h0, h1);
    *reinterpret_cast<uint32_t*>(&g_Wsplit[1][k][lane * 2]) = pack2(m0, m1);
    if (lane == 0)
        g_bias[k] = -0.5f * s;
}

// issue cp.async for window w (codes [kbase, kbase+128)), 2 splits
__device__ __forceinline__ void prefetch_win(uint32_t sbase, int w, int kbase, int tid) {
    const char* gw = reinterpret_cast<const char*>(g_Wsplit);
    const uint32_t base = sbase + (((w & 1) == 0) ? SM_BUF1 : 0);
#pragma unroll
    for (int t = 0; t < 8; t++) {
        int i = tid + t * THREADS;                 // 0..2047
        int split = i >> 10, rem = i & 1023;
        int n = rem >> 3, ch = rem & 7;
        uint32_t dst = base + split * SPLIT_W + n * ROWB + ch * 16;
        const char* src = gw + (((size_t)split * NCODE + kbase + n) * 8 + ch) * 16;
        CP_ASYNC16(dst, src);
    }
    if (tid < 32)
        CP_ASYNC16(sbase + SM_BIAS + (w & 1) * 512 + tid * 16,
                   reinterpret_cast<const char*>(g_bias) + (size_t)kbase * 4 + tid * 16);
    CP_COMMIT();
}

// ---- main kernel ------------------------------------------------------------
__global__ __launch_bounds__(THREADS, 2)
void vq_kernel(const float* __restrict__ x,
               const float* __restrict__ W,
               float* __restrict__ out) {
    extern __shared__ char smem[];
    const uint32_t sbase = smem_to_u32(smem);
    const int tid  = threadIdx.x;
    const int lane = tid & 31;
    const int wid  = tid >> 5;
    const int wm   = wid * 16;          // 16 rows per warp

    prefetch_win(sbase, 0, 0, tid);     // window 0 -> dedicated buffer

    // ---- stage A rows into [0, 36864) (h,m splits) ----
    {
        const int row = tid >> 1, half = tid & 1;
        const float4* xr = reinterpret_cast<const float4*>(
            x + ((size_t)blockIdx.x * MCTA + row) * DIM + half * 32);
        char* a0 = smem + row * ROWB + half * 64;
#pragma unroll
        for (int i = 0; i < 8; i++) {
            float4 v = xr[i];
            __nv_bfloat16 h0, m0, h1, m1, h2, m2, h3, m3;
            split2(v.x, h0, m0); split2(v.y, h1, m1);
            split2(v.z, h2, m2); split2(v.w, h3, m3);
            *reinterpret_cast<uint32_t*>(a0 + i * 8)               = pack2(h0, h1);
            *reinterpret_cast<uint32_t*>(a0 + i * 8 + 4)           = pack2(h2, h3);
            *reinterpret_cast<uint32_t*>(a0 + SPLIT_A + i * 8)     = pack2(m0, m1);
            *reinterpret_cast<uint32_t*>(a0 + SPLIT_A + i * 8 + 4) = pack2(m2, m3);
        }
    }
    __syncthreads();

    // ---- A fragments (h,m) -> registers, persistent ----
    uint32_t Af[2][4][4];
    {
        const uint32_t aB = sbase + (uint32_t)(wm + (lane & 15)) * ROWB + (lane >> 4) * 16;
#pragma unroll
        for (int sa = 0; sa < 2; sa++)
#pragma unroll
            for (int k = 0; k < 4; k++)
                LDSM_X4(Af[sa][k][0], Af[sa][k][1], Af[sa][k][2], Af[sa][k][3],
                        aB + sa * SPLIT_A + k * 32);
    }

    // running top-2 per row-chain (q=0: row wm+(lane>>2), q=1: +8)
    float b1[2] = {-3.0e38f, -3.0e38f}, b2[2] = {-3.0e38f, -3.0e38f};
    int   i1[2] = {0, 0},               i2[2] = {1, 1};

    const uint32_t blane = (uint32_t)(((lane >> 4) & 1) * 8 + (lane & 7)) * ROWB
                         + ((lane >> 3) & 1) * 16;

    for (int w = 0; w < NWIN; w++) {
        CP_WAIT0();
        __syncthreads();
        if (w + 1 < NWIN)
            prefetch_win(sbase, w + 1, (w + 1) * WINDOW, tid);

        const uint32_t bufb = sbase + (((w & 1) == 0) ? SM_BUF1 : 0);
        const float* sBias = reinterpret_cast<const float*>(smem + SM_BIAS + (w & 1) * 512);

#pragma unroll
        for (int sc = 0; sc < 2; sc++) {       // two 64-code sub-chunks
            float acc[8][4];
#pragma unroll
            for (int nt = 0; nt < 8; nt++) {
                float2 bb = *reinterpret_cast<const float2*>(
                    &sBias[sc * 64 + nt * 8 + (lane & 3) * 2]);
                acc[nt][0] = bb.x; acc[nt][1] = bb.y;
                acc[nt][2] = bb.x; acc[nt][3] = bb.y;
            }

            const uint32_t bbc = bufb + sc * 64 * ROWB + blane;
#pragma unroll
            for (int k = 0; k < 4; k++) {
#pragma unroll
                for (int np = 0; np < 2; np++) {
                    uint32_t Bh0[4], Bh1[4], Bm0[4], Bm1[4];
                    uint32_t bB = bbc + np * 32 * ROWB + k * 32;
                    LDSM_X4(Bh0[0], Bh0[1], Bh0[2], Bh0[3], bB);
                    LDSM_X4(Bh1[0], Bh1[1], Bh1[2], Bh1[3], bB + 16 * ROWB);
                    LDSM_X4(Bm0[0], Bm0[1], Bm0[2], Bm0[3], bB + SPLIT_W);
                    LDSM_X4(Bm1[0], Bm1[1], Bm1[2], Bm1[3], bB + SPLIT_W + 16 * ROWB);
                    // hh
                    MMA_BF16(acc[4 * np + 0], Af[0][k], Bh0);
                    MMA_BF16(acc[4 * np + 1], Af[0][k], Bh0 + 2);
                    MMA_BF16(acc[4 * np + 2], Af[0][k], Bh1);
                    MMA_BF16(acc[4 * np + 3], Af[0][k], Bh1 + 2);
                    // mh
                    MMA_BF16(acc[4 * np + 0], Af[1][k], Bh0);
                    MMA_BF16(acc[4 * np + 1], Af[1][k], Bh0 + 2);
                    MMA_BF16(acc[4 * np + 2], Af[1][k], Bh1);
                    MMA_BF16(acc[4 * np + 3], Af[1][k], Bh1 + 2);
                    // hm
                    MMA_BF16(acc[4 * np + 0], Af[0][k], Bm0);
                    MMA_BF16(acc[4 * np + 1], Af[0][k], Bm0 + 2);
                    MMA_BF16(acc[4 * np + 2], Af[0][k], Bm1);
                    MMA_BF16(acc[4 * np + 3], Af[0][k], Bm1 + 2);
                }
            }

            // ---- branchless keyed top-2 per chain ----
            const int nbase = w * WINDOW + sc * 64;
#pragma unroll
            for (int q = 0; q < 2; q++) {
                float h[8], l[8];
#pragma unroll
                for (int nt = 0; nt < 8; nt++) {
                    float e0 = embed4(acc[nt][q * 2 + 0], nt * 2 + 0);
                    float e1 = embed4(acc[nt][q * 2 + 1], nt * 2 + 1);
                    h[nt] = fmaxf(e0, e1);
                    l[nt] = fminf(e0, e1);
                }
#pragma unroll
                for (int s = 1; s < 8; s <<= 1)
#pragma unroll
                    for (int i = 0; i < 8; i += 2 * s) {
                        float hm = fminf(h[i], h[i + s]);
                        h[i] = fmaxf(h[i], h[i + s]);
                        l[i] = fmaxf(hm, fmaxf(l[i], l[i + s]));
                    }
                int lid1 = (int)(__float_as_uint(h[0]) & 15u);
                int lid2 = (int)(__float_as_uint(l[0]) & 15u);
                float v1 = h[0], v2 = l[0];
                int n1 = nbase + (lid1 >> 1) * 8 + (lane & 3) * 2 + (lid1 & 1);
                int n2 = nbase + (lid2 >> 1) * 8 + (lane & 3) * 2 + (lid2 & 1);
                bool w1 = v1 > b1[q];
                float c  = w1 ? b1[q] : v1;    int ci  = w1 ? i1[q] : n1;
                float s2 = w1 ? v2    : b2[q]; int s2i = w1 ? n2    : i2[q];
                b1[q] = w1 ? v1 : b1[q];       i1[q] = w1 ? n1 : i1[q];
                bool cw = c > s2;
                b2[q] = cw ? c : s2;           i2[q] = cw ? ci : s2i;
            }
        }
    }

    // ---- quad merge: global top-2 per row across the 4 lanes ----
#pragma unroll
    for (int q = 0; q < 2; q++) {
#pragma unroll
        for (int off = 1; off < 4; off <<= 1) {
            float ob1 = __shfl_xor_sync(0xFFFFFFFFu, b1[q], off);
            int   oi1 = __shfl_xor_sync(0xFFFFFFFFu, i1[q], off);
            float ob2 = __shfl_xor_sync(0xFFFFFFFFu, b2[q], off);
            int   oi2 = __shfl_xor_sync(0xFFFFFFFFu, i2[q], off);
            bool ow = beats(ob1, oi1, b1[q], i1[q]);
            float nv1 = ow ? ob1 : b1[q];  int ni1 = ow ? oi1 : i1[q];
            float cv  = ow ? b1[q] : ob1;  int ci  = ow ? i1[q] : oi1;
            float sv  = ow ? ob2 : b2[q];  int si  = ow ? oi2 : i2[q];
            bool cw = beats(cv, ci, sv, si);
            b1[q] = nv1; i1[q] = ni1;
            b2[q] = cw ? cv : sv; i2[q] = cw ? ci : si;
        }
    }

    // ---- exact fp32 rescore of the two candidates ----
    int Kf[2];
#pragma unroll
    for (int q = 0; q < 2; q++) {
        const int r = wm + (lane >> 2) + q * 8;
        const size_t grow = (size_t)blockIdx.x * MCTA + r;
        const int c1 = i1[q], c2 = i2[q];
        float d1 = 0.0f, d2 = 0.0f;
#pragma unroll
        for (int k = 0; k < 4; k++)
#pragma unroll
            for (int ch = 0; ch < 2; ch++) {
                const int c0 = 2 * (lane & 3) + ch * 8 + 16 * k;
                float2 xx = *reinterpret_cast<const float2*>(x + grow * DIM + c0);
                float2 w1 = __ldg(reinterpret_cast<const float2*>(W + (size_t)c1 * DIM + c0));
                float2 w2 = __ldg(reinterpret_cast<const float2*>(W + (size_t)c2 * DIM + c0));
                d1 = fmaf(xx.x, w1.x, fmaf(xx.y, w1.y, d1));
                d2 = fmaf(xx.x, w2.x, fmaf(xx.y, w2.y, d2));
            }
        d1 += __shfl_xor_sync(0xFFFFFFFFu, d1, 1);
        d1 += __shfl_xor_sync(0xFFFFFFFFu, d1, 2);
        d2 += __shfl_xor_sync(0xFFFFFFFFu, d2, 1);
        d2 += __shfl_xor_sync(0xFFFFFFFFu, d2, 2);
        float s1 = d1 + __ldg(&g_bias[c1]);
        float s2 = d2 + __ldg(&g_bias[c2]);
        Kf[q] = beats(s1, c1, s2, c2) ? c1 : c2;
    }

    // ---- gather codewords + write outputs ----
    const int lq = lane & 3;   // dim slice lq*16 .. lq*16+15
#pragma unroll
    for (int q = 0; q < 2; q++) {
        const int r = wm + (lane >> 2) + q * 8;
        const size_t grow = (size_t)blockIdx.x * MCTA + r;
        const int K = Kf[q];
        const float4* wsrc = reinterpret_cast<const float4*>(W + (size_t)K * DIM + lq * 16);
        float4* o1 = reinterpret_cast<float4*>(out + grow * DIM + lq * 16);
        float4* o2 = reinterpret_cast<float4*>(out + ((size_t)NROWS + grow) * DIM + lq * 16);
#pragma unroll
        for (int i = 0; i < 4; i++) {
            float4 v = wsrc[i];
            o1[i] = v;
            o2[i] = v;
        }
        if (lq == 0)
            out[(size_t)2 * NROWS * DIM + grow] = (float)K;
    }
}

// ---- launch -----------------------------------------------------------------
extern "C" void kernel_launch(void* const* d_in, const int* in_sizes, int n_in,
                              void* d_out, int out_size) {
    const float* x = (const float*)d_in[0];
    const float* W = (const float*)d_in[1];
    float* out = (float*)d_out;

    cudaFuncSetAttribute(vq_kernel, cudaFuncAttributeMaxDynamicSharedMemorySize, SMEM_TOTAL);
    prep_kernel<<<(NCODE * 32) / 256, 256>>>(W);
    vq_kernel<<<NROWS / MCTA, THREADS, SMEM_TOTAL>>>(x, W, out);
}